// round 1
// baseline (speedup 1.0000x reference)
#include <cuda_runtime.h>
#include <math.h>

#define Bq 32
#define Dq 128
#define Hq 256
#define Oq 10

// Scratch (allocation-free rule: __device__ globals)
__device__ float g_C[Hq*Hq];        // W1^T W1
__device__ float g_K[Bq*Oq*Hq];     // K[b][o][g]
__device__ float g_u[Bq*Hq];
__device__ float g_G2[Bq*Oq*Oq];    // J J^T
__device__ float g_num[Bq*Dq];      // un-normalized a numerator
__device__ float g_nv[Bq];          // ||v|| + 1e-6
__device__ float g_part[Bq*8];      // N2 partial sums (deterministic, no atomics)

// ---------------- Kernel A: C = W1^T W1 (batch independent) ----------------
__global__ void kA(const float* __restrict__ W1) {
    int h = blockIdx.x, g = threadIdx.x;
    float acc = 0.f;
    #pragma unroll 8
    for (int d = 0; d < Dq; d++)
        acc += W1[d*Hq + h] * W1[d*Hq + g];
    g_C[h*Hq + g] = acc;
}

// ---------------- Kernel B1: per-batch preamble --------------------------
// s,u,w, K = (diag(s)W2)^T C, G2 = JJ^T, a-numerator, ||v||
__global__ void kB1(const float* __restrict__ t, const float* __restrict__ sb,
                    const float* __restrict__ x0, const float* __restrict__ x1,
                    const float* __restrict__ W1, const float* __restrict__ b1,
                    const float* __restrict__ W2) {
    int b = blockIdx.x, tid = threadIdx.x;
    __shared__ __align__(16) float ssw2[Hq*12];   // s_h * W2[h][o], pad 12
    __shared__ __align__(16) float sKT[Hq*12];    // K^T[g][o], pad 12
    __shared__ float sx[Dq], sv[Dq], ss[Hq], su[Hq], sw[Hq], sp[Hq];
    __shared__ float sG2[Oq*Oq], sc[Oq];

    float tt = t[0];
    float window = 4.f*tt*(1.f-tt);
    if (tid < Dq) {
        float dev = sb[b*Dq + tid];
        float a0v = x0[b*Dq + tid];
        sx[tid] = a0v + tt*(x1[b*Dq+tid]-a0v) + window*dev;
        sv[tid] = sb[Bq*Dq + b*Dq + tid];
    }
    __syncthreads();

    if (tid < 32) {  // ||v||
        float acc = 0.f;
        for (int d = tid; d < Dq; d += 32) { float v = sv[d]; acc += v*v; }
        #pragma unroll
        for (int o = 16; o; o >>= 1) acc += __shfl_xor_sync(0xffffffffu, acc, o);
        if (tid == 0) g_nv[b] = sqrtf(acc) + 1e-6f;
    }

    // z_h = b1 + x.W1[:,h] ; w_h = v.W1[:,h]   (thread = h)
    float z = b1[tid], w = 0.f;
    #pragma unroll 8
    for (int d = 0; d < Dq; d++) {
        float wv = W1[d*Hq + tid];
        z += sx[d]*wv; w += sv[d]*wv;
    }
    float th = tanhf(z);
    float s  = 1.f - th*th;
    float u  = -2.f*th*s;
    ss[tid]=s; su[tid]=u; sw[tid]=w;
    g_u[b*Hq+tid]=u;
    float w2r[Oq];
    #pragma unroll
    for (int o=0;o<Oq;o++){ w2r[o]=W2[tid*Oq+o]; ssw2[tid*12+o]=s*w2r[o]; }
    ssw2[tid*12+10]=0.f; ssw2[tid*12+11]=0.f;
    __syncthreads();

    // K[o][g] = sum_h (s_h W2[h][o]) C[h][g]   (thread = g)
    float kreg[Oq];
    #pragma unroll
    for (int o=0;o<Oq;o++) kreg[o]=0.f;
    for (int h=0; h<Hq; h++) {
        float c = g_C[h*Hq + tid];                 // coalesced, L2 resident
        const float4* pp = (const float4*)&ssw2[h*12];
        float4 a0=pp[0], a1=pp[1], a2=pp[2];
        kreg[0]+=c*a0.x; kreg[1]+=c*a0.y; kreg[2]+=c*a0.z; kreg[3]+=c*a0.w;
        kreg[4]+=c*a1.x; kreg[5]+=c*a1.y; kreg[6]+=c*a1.z; kreg[7]+=c*a1.w;
        kreg[8]+=c*a2.x; kreg[9]+=c*a2.y;
    }
    #pragma unroll
    for (int o=0;o<Oq;o++){ g_K[(b*Oq+o)*Hq + tid]=kreg[o]; sKT[tid*12+o]=kreg[o]; }
    sKT[tid*12+10]=0.f; sKT[tid*12+11]=0.f;
    __syncthreads();

    // G2[o][p] = sum_g K[o][g] * (s_g W2[g][p])  and  c_o = sum_h W2[h][o] u_h w_h^2
    if (tid < Oq*Oq) {
        int o = tid/Oq, p = tid%Oq;
        float acc=0.f;
        for (int g=0; g<Hq; g++) acc += sKT[g*12+o]*ssw2[g*12+p];
        sG2[tid]=acc; g_G2[b*Oq*Oq+tid]=acc;
    } else if (tid >= 128 && tid < 128+Oq) {
        int o = tid-128;
        float acc=0.f;
        for (int h=0; h<Hq; h++) acc += W2[h*Oq+o]*su[h]*sw[h]*sw[h];
        sc[o]=acc;
    }
    __syncthreads();

    // sp_g = s_g * (W2 c)_g
    {
        float p=0.f;
        #pragma unroll
        for (int o=0;o<Oq;o++) p += w2r[o]*sc[o];
        sp[tid] = ss[tid]*p;
    }
    __syncthreads();

    // num_i = sum_g sp_g W1[i][g]   (warp-per-row, coalesced)
    int warp = tid>>5, lane = tid&31;
    for (int r=0;r<16;r++){
        int i = warp*16 + r;
        float acc=0.f;
        #pragma unroll
        for (int g=lane; g<Hq; g+=32) acc += sp[g]*W1[i*Hq+g];
        #pragma unroll
        for (int o=16;o;o>>=1) acc += __shfl_xor_sync(0xffffffffu,acc,o);
        if (lane==0) g_num[b*Dq+i]=acc;
    }
}

// ---------------- Kernel B2: N2 = 2*sum_{hg} u_h u_g C_hg (C_hg*qq + R_hg R_gh)
// grid = 32 batches x 8 h-splits
__global__ void kB2(const float* __restrict__ W2) {
    int b = blockIdx.x >> 3, split = blockIdx.x & 7;
    int h0 = split*32;
    int g = threadIdx.x;
    __shared__ __align__(16) float sWU[32*12];  // W2 row of h + u_h at [10]
    __shared__ __align__(16) float sKT[32*12];  // K[:,h]
    __shared__ float sG2[Oq*Oq];
    __shared__ float sred[8];

    if (g < Oq*Oq) sG2[g] = g_G2[b*Oq*Oq+g];
    if (g >= 128 && g < 160) {
        int hh = g-128, h = h0+hh;
        #pragma unroll
        for (int o=0;o<Oq;o++){ sWU[hh*12+o]=W2[h*Oq+o]; sKT[hh*12+o]=g_K[(b*Oq+o)*Hq+h]; }
        sWU[hh*12+10]=g_u[b*Hq+h]; sWU[hh*12+11]=0.f;
        sKT[hh*12+10]=0.f; sKT[hh*12+11]=0.f;
    }
    float u_g = g_u[b*Hq+g];
    float kcol[Oq], w2g[Oq];
    #pragma unroll
    for (int o=0;o<Oq;o++){ kcol[o]=g_K[(b*Oq+o)*Hq+g]; w2g[o]=W2[g*Oq+o]; }
    __syncthreads();

    float wg[Oq];   // wg[o] = sum_p G2[o][p] W2[g][p]
    #pragma unroll
    for (int o=0;o<Oq;o++){
        float a=0.f;
        #pragma unroll
        for (int p=0;p<Oq;p++) a += sG2[o*Oq+p]*w2g[p];
        wg[o]=a;
    }

    float acc = 0.f;
    for (int hh=0; hh<32; hh++) {
        int h = h0+hh;
        float c = g_C[h*Hq+g];
        const float4* pa = (const float4*)&sWU[hh*12];
        float4 a0=pa[0], a1=pa[1], a2=pa[2];
        const float4* pb = (const float4*)&sKT[hh*12];
        float4 b0=pb[0], b1v=pb[1], b2v=pb[2];
        float qq  = a0.x*wg[0]+a0.y*wg[1]+a0.z*wg[2]+a0.w*wg[3]
                  + a1.x*wg[4]+a1.y*wg[5]+a1.z*wg[6]+a1.w*wg[7]
                  + a2.x*wg[8]+a2.y*wg[9];
        float rhg = a0.x*kcol[0]+a0.y*kcol[1]+a0.z*kcol[2]+a0.w*kcol[3]
                  + a1.x*kcol[4]+a1.y*kcol[5]+a1.z*kcol[6]+a1.w*kcol[7]
                  + a2.x*kcol[8]+a2.y*kcol[9];
        float rgh = w2g[0]*b0.x+w2g[1]*b0.y+w2g[2]*b0.z+w2g[3]*b0.w
                  + w2g[4]*b1v.x+w2g[5]*b1v.y+w2g[6]*b1v.z+w2g[7]*b1v.w
                  + w2g[8]*b2v.x+w2g[9]*b2v.y;
        acc += a2.z*u_g*(c*(c*qq + rhg*rgh));   // a2.z = u_h
    }
    #pragma unroll
    for (int o=16;o;o>>=1) acc += __shfl_xor_sync(0xffffffffu,acc,o);
    if ((g&31)==0) sred[g>>5]=acc;
    __syncthreads();
    if (g==0){
        float tt=0.f;
        #pragma unroll
        for (int i=0;i<8;i++) tt+=sred[i];
        g_part[b*8+split]=tt;
    }
}

// ---------------- Kernel B3: finalize + write output ----------------------
__global__ void kB3(const float* __restrict__ sb, float* __restrict__ out) {
    int b = blockIdx.x, i = threadIdx.x;
    __shared__ float sscale;
    if (i == 0) {
        float n2 = 0.f;
        #pragma unroll
        for (int k=0;k<8;k++) n2 += g_part[b*8+k];
        n2 *= 2.f;
        float nF = sqrtf(fmaxf(n2, 0.f)) + 1e-6f;
        sscale = -1.f/(nF * g_nv[b]);
    }
    __syncthreads();
    out[b*Dq + i] = sb[Bq*Dq + b*Dq + i];                       // dev_velocity
    out[Bq*Dq + b*Dq + i] = g_num[b*Dq+i]*sscale - 0.1f*sb[b*Dq+i]; // a + restoration
}

extern "C" void kernel_launch(void* const* d_in, const int* in_sizes, int n_in,
                              void* d_out, int out_size) {
    const float* t  = (const float*)d_in[0];
    const float* sb = (const float*)d_in[1];
    const float* x0 = (const float*)d_in[2];
    const float* x1 = (const float*)d_in[3];
    const float* W1 = (const float*)d_in[4];
    const float* b1 = (const float*)d_in[5];
    const float* W2 = (const float*)d_in[6];
    // b2 (d_in[7]) drops out of all Jacobians — unused.
    float* out = (float*)d_out;

    kA <<<Hq, Hq>>>(W1);
    kB1<<<Bq, Hq>>>(t, sb, x0, x1, W1, b1, W2);
    kB2<<<Bq*8, Hq>>>(W2);
    kB3<<<Bq, Dq>>>(sb, out);
}